// round 8
// baseline (speedup 1.0000x reference)
#include <cuda_runtime.h>
#include <math.h>
#include <stdint.h>

// RoPE: X (L=2048, D=4096, N=4) fp32, row-major.
// out[:, :half]  = cos*x1 - sin*x2 ; out[:, half:] = sin*x1 + cos*x2
// theta_i = 10000^(i/2048), ang = (l+1)*theta_i  (fp32 in the reference)
//
// 256-bit (v8.b32) loads/stores: each thread owns rotary pair (2j, 2j+1)
// for G consecutive l's -> every global access is a 32B-aligned 256-bit op,
// 1KB per warp instruction, streaming (.cs) both ways.

#define L_DIM 2048
#define D4    4096      // float4s per l-row
#define HALF  2048      // float4 offset of the second half
#define G     2         // l-values per thread

struct ThetaC { float hi[11]; float lo[11]; };

__device__ __forceinline__ void ld256(const float4* p, uint32_t* r) {
    asm volatile("ld.global.cs.v8.b32 {%0,%1,%2,%3,%4,%5,%6,%7}, [%8];"
                 : "=r"(r[0]), "=r"(r[1]), "=r"(r[2]), "=r"(r[3]),
                   "=r"(r[4]), "=r"(r[5]), "=r"(r[6]), "=r"(r[7])
                 : "l"(p));
}
__device__ __forceinline__ void st256(float4* p, const uint32_t* r) {
    asm volatile("st.global.cs.v8.b32 [%0], {%1,%2,%3,%4,%5,%6,%7,%8};"
                 :: "l"(p),
                    "r"(r[0]), "r"(r[1]), "r"(r[2]), "r"(r[3]),
                    "r"(r[4]), "r"(r[5]), "r"(r[6]), "r"(r[7]));
}

__global__ __launch_bounds__(256)
void rope_kernel(const float4* __restrict__ X, float4* __restrict__ out, ThetaC tc) {
    int t  = blockIdx.x * blockDim.x + threadIdx.x;   // 0 .. (L/G)*(HALF/2) - 1
    int j  = t & 1023;                                // rotary pair index
    int l0 = (t >> 10) * G;                           // first l for this thread
    int i0 = j << 1;                                  // even rotary index

    // ---- front-batched 256-bit streaming loads --------------------------
    int base = l0 * D4 + i0;                          // float4 units, even -> 32B aligned
    uint32_t a[G][8], b[G][8];
    #pragma unroll
    for (int g = 0; g < G; g++) {
        ld256(&X[base + g * D4],        a[g]);        // X[l, 2j..2j+1, 0..3]
        ld256(&X[base + g * D4 + HALF], b[g]);        // X[l, 2j+HALF.., 0..3]
    }

    // ---- double-float theta for i0 and i0+1 -----------------------------
    float th = 1.0f, tl = 0.0f;
    #pragma unroll
    for (int k = 1; k < 11; k++) {
        if (i0 & (1 << k)) {
            float bh = tc.hi[k], bl = tc.lo[k];
            float p  = th * bh;
            float e  = fmaf(th, bh, -p);
            e        = fmaf(th, bl, e);
            e        = fmaf(tl, bh, e);
            float s  = p + e;
            tl       = (p - s) + e;
            th       = s;
        }
    }
    float theta_e = th + tl;                          // theta(2j)
    {   // multiply by c0 for theta(2j+1)
        float bh = tc.hi[0], bl = tc.lo[0];
        float p  = th * bh;
        float e  = fmaf(th, bh, -p);
        e        = fmaf(th, bl, e);
        e        = fmaf(tl, bh, e);
        float s  = p + e;
        tl       = (p - s) + e;
        th       = s;
    }
    float theta_o = th + tl;                          // theta(2j+1)

    // ---- rotate + 256-bit streaming stores -------------------------------
    #pragma unroll
    for (int g = 0; g < G; g++) {
        float pos = (float)(l0 + g + 1);

        float sc[2], cc[2];
        #pragma unroll
        for (int par = 0; par < 2; par++) {
            float ang = pos * (par ? theta_o : theta_e);   // one fp32 multiply
            double ad = (double)ang;                        // exact
            double q  = rint(ad * 0.15915494309189535);     // 1/(2*pi)
            float  r  = (float)fma(q, -6.283185307179586, ad);
            sincosf(r, &sc[par], &cc[par]);
        }

        uint32_t o1[8], o2[8];
        #pragma unroll
        for (int e = 0; e < 8; e++) {
            int par = e >> 2;                              // 0..3 -> even, 4..7 -> odd
            float av = __uint_as_float(a[g][e]);
            float bv = __uint_as_float(b[g][e]);
            o1[e] = __float_as_uint(cc[par] * av - sc[par] * bv);
            o2[e] = __float_as_uint(sc[par] * av + cc[par] * bv);
        }
        st256(&out[base + g * D4],        o1);
        st256(&out[base + g * D4 + HALF], o2);
    }
}

extern "C" void kernel_launch(void* const* d_in, const int* in_sizes, int n_in,
                              void* d_out, int out_size) {
    const float4* X   = (const float4*)d_in[0];
    float4*       out = (float4*)d_out;

    ThetaC tc;
    for (int k = 0; k < 11; k++) {
        double c = pow(10000.0, (double)(1 << k) / 2048.0);
        tc.hi[k] = (float)c;
        tc.lo[k] = (float)(c - (double)tc.hi[k]);
    }

    int total = (L_DIM / G) * (HALF / 2);     // 1,048,576 threads
    rope_kernel<<<total / 256, 256>>>(X, out, tc);
}